// round 2
// baseline (speedup 1.0000x reference)
#include <cuda_runtime.h>

#define N_NODES 8192
#define IN_F 512
#define OUT_F 512
#define NSUB 8

// ---------------- scratch (static __device__ — no allocation) ----------------
__device__ int       d_perm[N_NODES];
__device__ int       d_cnt[NSUB];
__device__ int       d_off[NSUB + 1];
__device__ long long d_abase[NSUB];
__device__ float     d_Sg[(size_t)N_NODES * OUT_F];          // gathered support (permuted rows)
__device__ float     d_Ag[(size_t)N_NODES * N_NODES];        // gathered adj blocks (worst case)

// ---------------- kernel 0: counting sort of labels -> permutation ----------------
__global__ void build_perm(const int* __restrict__ labels) {
    __shared__ int cnt[NSUB][257];
    __shared__ int offs[NSUB];
    int t = threadIdx.x;  // 256 threads, 32 labels each

    int local[NSUB];
#pragma unroll
    for (int s = 0; s < NSUB; s++) local[s] = 0;

    int myl[32];
#pragma unroll
    for (int i = 0; i < 32; i++) {
        int l = labels[t * 32 + i];
        myl[i] = l;
        local[l]++;
    }
#pragma unroll
    for (int s = 0; s < NSUB; s++) cnt[s][t] = local[s];
    __syncthreads();

    if (t < NSUB) {
        int sum = 0;
        for (int i = 0; i < 256; i++) { int v = cnt[t][i]; cnt[t][i] = sum; sum += v; }
        cnt[t][256] = sum;  // total count for subspace t
    }
    __syncthreads();

    if (t == 0) {
        int acc = 0;
        long long ab = 0;
        for (int s = 0; s < NSUB; s++) {
            d_off[s] = acc;
            offs[s] = acc;
            int ns = cnt[s][256];
            d_cnt[s] = ns;
            d_abase[s] = ab;
            ab += (long long)ns * ns;
            acc += ns;
        }
        d_off[NSUB] = acc;
    }
    __syncthreads();

    int base[NSUB];
#pragma unroll
    for (int s = 0; s < NSUB; s++) base[s] = offs[s] + cnt[s][t];
#pragma unroll
    for (int i = 0; i < 32; i++) {
        int l = myl[i];
        d_perm[base[l]++] = t * 32 + i;   // stable: thread order x item order
    }
}

// ---------------- kernel 1: gather adj blocks (coalesced writes) ----------------
__global__ void gather_adj(const float* __restrict__ adj, const int* __restrict__ labels) {
    int r = blockIdx.x;                       // permuted row index
    int pr = d_perm[r];
    int s = labels[pr];
    int off = d_off[s];
    int ns = d_cnt[s];
    long long base = d_abase[s] + (long long)(r - off) * ns;
    const float* __restrict__ arow = adj + (long long)pr * N_NODES;
    const int* __restrict__ pcol = d_perm + off;
    for (int c = threadIdx.x; c < ns; c += blockDim.x)
        d_Ag[base + c] = __ldg(arow + pcol[c]);
}

// ---------------- kernel 2: Sg = X[perm] @ W[s] (per subspace) ----------------
// 128x128 tile, BK=8, 256 threads, 8x8 microtile (2x2 float4 fragments)
__global__ __launch_bounds__(256, 2) void gemm1(const float* __restrict__ X,
                                                const float* __restrict__ W) {
    int s = blockIdx.z;
    int ns = d_cnt[s];
    int row0 = blockIdx.x * 128;
    if (row0 >= ns) return;
    int col0 = blockIdx.y * 128;
    int off = d_off[s];

    __shared__ float As[8][128];
    __shared__ float Bs[8][128];

    int tid = threadIdx.x;
    int tx = tid & 15, ty = tid >> 4;

    float acc[8][8];
#pragma unroll
    for (int i = 0; i < 8; i++)
#pragma unroll
        for (int j = 0; j < 8; j++) acc[i][j] = 0.f;

    // A tile loads: thread -> (row = tid/2, 4 consecutive k at (tid&1)*4)
    int la_r = tid >> 1;
    int la_k = (tid & 1) * 4;
    const float* aptr = nullptr;
    if (row0 + la_r < ns) aptr = X + (size_t)d_perm[off + row0 + la_r] * IN_F;

    // B tile loads: thread -> (k = tid/32, 4 consecutive cols at (tid&31)*4)
    int lb_k = tid >> 5;
    int lb_c = (tid & 31) * 4;
    const float* Wp = W + (size_t)s * IN_F * OUT_F + (size_t)lb_k * OUT_F + col0 + lb_c;

    for (int k0 = 0; k0 < IN_F; k0 += 8) {
        float4 av = make_float4(0.f, 0.f, 0.f, 0.f);
        if (aptr) av = *(const float4*)(aptr + k0 + la_k);
        As[la_k + 0][la_r] = av.x;
        As[la_k + 1][la_r] = av.y;
        As[la_k + 2][la_r] = av.z;
        As[la_k + 3][la_r] = av.w;

        *(float4*)&Bs[lb_k][lb_c] = *(const float4*)(Wp + (size_t)k0 * OUT_F);
        __syncthreads();

#pragma unroll
        for (int k = 0; k < 8; k++) {
            float ar[8], br[8];
            *(float4*)&ar[0] = *(const float4*)&As[k][ty * 4];
            *(float4*)&ar[4] = *(const float4*)&As[k][64 + ty * 4];
            *(float4*)&br[0] = *(const float4*)&Bs[k][tx * 4];
            *(float4*)&br[4] = *(const float4*)&Bs[k][64 + tx * 4];
#pragma unroll
            for (int i = 0; i < 8; i++)
#pragma unroll
                for (int j = 0; j < 8; j++) acc[i][j] += ar[i] * br[j];
        }
        __syncthreads();
    }

#pragma unroll
    for (int i = 0; i < 8; i++) {
        int r = (i < 4) ? (ty * 4 + i) : (64 + ty * 4 + (i - 4));
        int grow = row0 + r;
        if (grow < ns) {
            float* o = d_Sg + (size_t)(off + grow) * OUT_F + col0;
            *(float4*)(o + tx * 4)      = make_float4(acc[i][0], acc[i][1], acc[i][2], acc[i][3]);
            *(float4*)(o + 64 + tx * 4) = make_float4(acc[i][4], acc[i][5], acc[i][6], acc[i][7]);
        }
    }
}

// ---------------- kernel 3: out[perm[r]] = Ag_s @ Sg_s (per subspace) ----------------
__global__ __launch_bounds__(256, 2) void gemm2(float* __restrict__ out) {
    int s = blockIdx.z;
    int ns = d_cnt[s];
    int row0 = blockIdx.x * 128;
    if (row0 >= ns) return;
    int col0 = blockIdx.y * 128;
    int off = d_off[s];
    long long abase = d_abase[s];

    __shared__ float As[8][128];
    __shared__ float Bs[8][128];

    int tid = threadIdx.x;
    int tx = tid & 15, ty = tid >> 4;

    float acc[8][8];
#pragma unroll
    for (int i = 0; i < 8; i++)
#pragma unroll
        for (int j = 0; j < 8; j++) acc[i][j] = 0.f;

    int la_r = tid >> 1;
    int la_k = (tid & 1) * 4;
    const float* aptr = nullptr;
    if (row0 + la_r < ns) aptr = d_Ag + abase + (long long)(row0 + la_r) * ns;

    int lb_k = tid >> 5;
    int lb_c = (tid & 31) * 4;

    int ktiles = (ns + 7) >> 3;
    for (int kt = 0; kt < ktiles; kt++) {
        int k0 = kt * 8;
        // A: scalar loads (ld = ns, arbitrary alignment), guarded on K
#pragma unroll
        for (int j = 0; j < 4; j++) {
            int k = k0 + la_k + j;
            As[la_k + j][la_r] = (aptr && k < ns) ? aptr[k] : 0.f;
        }
        // B: Sg row (aligned, ld = 512), guarded on K
        float4 bv = make_float4(0.f, 0.f, 0.f, 0.f);
        int kb = k0 + lb_k;
        if (kb < ns) bv = *(const float4*)(d_Sg + (size_t)(off + kb) * OUT_F + col0 + lb_c);
        *(float4*)&Bs[lb_k][lb_c] = bv;
        __syncthreads();

#pragma unroll
        for (int k = 0; k < 8; k++) {
            float ar[8], br[8];
            *(float4*)&ar[0] = *(const float4*)&As[k][ty * 4];
            *(float4*)&ar[4] = *(const float4*)&As[k][64 + ty * 4];
            *(float4*)&br[0] = *(const float4*)&Bs[k][tx * 4];
            *(float4*)&br[4] = *(const float4*)&Bs[k][64 + tx * 4];
#pragma unroll
            for (int i = 0; i < 8; i++)
#pragma unroll
                for (int j = 0; j < 8; j++) acc[i][j] += ar[i] * br[j];
        }
        __syncthreads();
    }

#pragma unroll
    for (int i = 0; i < 8; i++) {
        int r = (i < 4) ? (ty * 4 + i) : (64 + ty * 4 + (i - 4));
        int grow = row0 + r;
        if (grow < ns) {
            float* o = out + (size_t)d_perm[off + grow] * OUT_F + col0;
            *(float4*)(o + tx * 4)      = make_float4(acc[i][0], acc[i][1], acc[i][2], acc[i][3]);
            *(float4*)(o + 64 + tx * 4) = make_float4(acc[i][4], acc[i][5], acc[i][6], acc[i][7]);
        }
    }
}

// ---------------- launch ----------------
extern "C" void kernel_launch(void* const* d_in, const int* in_sizes, int n_in,
                              void* d_out, int out_size) {
    const float* X      = (const float*)d_in[0];   // [8192, 512]
    const float* adj    = (const float*)d_in[1];   // [8192, 8192]
    const int*   labels = (const int*)d_in[2];     // [8192]
    const float* W      = (const float*)d_in[3];   // [8, 512, 512]
    float* out = (float*)d_out;                    // [8192, 512]

    build_perm<<<1, 256>>>(labels);
    gather_adj<<<N_NODES, 256>>>(adj, labels);
    gemm1<<<dim3(N_NODES / 128, OUT_F / 128, NSUB), 256>>>(X, W);
    gemm2<<<dim3(N_NODES / 128, OUT_F / 128, NSUB), 256>>>(out);
}

// round 8
// speedup vs baseline: 3.0158x; 3.0158x over previous
#include <cuda_runtime.h>
#include <cuda_fp16.h>
#include <cstdint>

#define NN   8192
#define INF  512
#define OUTF 512
#define NSUB 8
#define TOTP 9216                 // 8192 + 8*128 slack, multiple of 128
#define AG_CAP 70000000           // worst-case sum of nsp^2

// ---------------- scratch (static __device__ — no allocation) ----------------
__device__ int       d_perm[NN];
__device__ int       d_cnt[NSUB];
__device__ int       d_off[NSUB + 1];    // real prefix
__device__ int       d_poff[NSUB + 1];   // padded prefix (multiples of 128)
__device__ long long d_abase[NSUB];      // padded Ag block bases
__device__ __half d_Xg[(size_t)TOTP * INF];                 // permuted, padded X (fp16)
__device__ __half d_Wt[(size_t)NSUB * OUTF * INF];          // W transposed [s][n][k] (fp16)
__device__ __half d_St[(size_t)OUTF * TOTP];                // support transposed [n][m] (fp16)
__device__ __half d_Ag[AG_CAP];                             // gathered adj * 8192 (fp16)

// ---------------- helpers ----------------
__device__ __forceinline__ uint32_t smem_u32(const void* p) {
    uint32_t a;
    asm("{ .reg .u64 t; cvta.to.shared.u64 t, %1; cvt.u32.u64 %0, t; }" : "=r"(a) : "l"(p));
    return a;
}
#define SW128(off) ((off) ^ (((off) >> 3) & 0x70))
#define CP_ASYNC16(sm, g) asm volatile("cp.async.cg.shared.global [%0], [%1], 16;" :: "r"(sm), "l"(g) : "memory")
#define CP_COMMIT()       asm volatile("cp.async.commit_group;" ::: "memory")

#define LDSM_X4(r0, r1, r2, r3, addr)                                             \
    asm volatile("ldmatrix.sync.aligned.m8n8.x4.shared.b16 {%0,%1,%2,%3}, [%4];"  \
                 : "=r"(r0), "=r"(r1), "=r"(r2), "=r"(r3) : "r"(addr))

#define MMA_F16(d, a, b)                                                          \
    asm volatile("mma.sync.aligned.m16n8k16.row.col.f32.f16.f16.f32 "             \
                 "{%0,%1,%2,%3}, {%4,%5,%6,%7}, {%8,%9}, {%0,%1,%2,%3};"          \
                 : "+f"((d)[0]), "+f"((d)[1]), "+f"((d)[2]), "+f"((d)[3])         \
                 : "r"((a)[0]), "r"((a)[1]), "r"((a)[2]), "r"((a)[3]),            \
                   "r"((b)[0]), "r"((b)[1]))

__device__ __forceinline__ int find_sub(int r) {
    int s = 0;
#pragma unroll
    for (int i = 0; i < NSUB - 1; i++) s += (r >= d_poff[i + 1]) ? 1 : 0;
    return s;
}

// ---------------- kernel 0: counting sort ----------------
__global__ void build_perm(const int* __restrict__ labels) {
    __shared__ int cnt[NSUB][257];
    __shared__ int offs[NSUB];
    int t = threadIdx.x;
    int local[NSUB];
#pragma unroll
    for (int s = 0; s < NSUB; s++) local[s] = 0;
    int myl[32];
#pragma unroll
    for (int i = 0; i < 32; i++) { int l = labels[t * 32 + i]; myl[i] = l; local[l]++; }
#pragma unroll
    for (int s = 0; s < NSUB; s++) cnt[s][t] = local[s];
    __syncthreads();
    if (t < NSUB) {
        int sum = 0;
        for (int i = 0; i < 256; i++) { int v = cnt[t][i]; cnt[t][i] = sum; sum += v; }
        cnt[t][256] = sum;
    }
    __syncthreads();
    if (t == 0) {
        int acc = 0, pacc = 0; long long ab = 0;
        for (int s = 0; s < NSUB; s++) {
            int ns = cnt[s][256];
            int nsp = (ns + 127) & ~127;
            d_off[s] = acc; offs[s] = acc; d_cnt[s] = ns;
            d_poff[s] = pacc; d_abase[s] = ab;
            acc += ns; pacc += nsp; ab += (long long)nsp * nsp;
        }
        d_off[NSUB] = acc; d_poff[NSUB] = pacc;
    }
    __syncthreads();
    int base[NSUB];
#pragma unroll
    for (int s = 0; s < NSUB; s++) base[s] = offs[s] + cnt[s][t];
#pragma unroll
    for (int i = 0; i < 32; i++) { int l = myl[i]; d_perm[base[l]++] = t * 32 + i; }
}

// ---------------- kernel 1: X gather -> fp16 (permuted, zero-padded) ----------------
__global__ void prep_X(const float* __restrict__ X) {
    int r = blockIdx.x;
    if (r >= d_poff[NSUB]) return;
    int s = find_sub(r);
    int local = r - d_poff[s];
    int k = threadIdx.x * 4;
    size_t dst = (size_t)r * INF + k;
    if (local < d_cnt[s]) {
        const float* src = X + (size_t)d_perm[d_off[s] + local] * INF;
        float4 v = *(const float4*)(src + k);
        d_Xg[dst + 0] = __float2half(v.x);
        d_Xg[dst + 1] = __float2half(v.y);
        d_Xg[dst + 2] = __float2half(v.z);
        d_Xg[dst + 3] = __float2half(v.w);
    } else {
        __half z = __float2half(0.f);
#pragma unroll
        for (int j = 0; j < 4; j++) d_Xg[dst + j] = z;
    }
}

// ---------------- kernel 2: W transpose -> fp16 [s][n][k] ----------------
__global__ void prep_W(const float* __restrict__ W) {
    __shared__ float tile[32][33];
    int s = blockIdx.z;
    int k0 = blockIdx.x * 32, n0 = blockIdx.y * 32;
    int tx = threadIdx.x, ty = threadIdx.y;   // (32, 8)
    const float* Ws = W + (size_t)s * INF * OUTF;
#pragma unroll
    for (int i = 0; i < 4; i++)
        tile[ty + 8 * i][tx] = Ws[(size_t)(k0 + ty + 8 * i) * OUTF + n0 + tx];
    __syncthreads();
#pragma unroll
    for (int i = 0; i < 4; i++) {
        float v = tile[tx][ty + 8 * i];                 // W[k0+tx][n0+ty+8i]
        size_t dst = ((size_t)s * OUTF + (n0 + ty + 8 * i)) * INF + k0 + tx;
        d_Wt[dst] = __float2half(v);
    }
}

// ---------------- kernel 3: adj gather (x8192) -> fp16, zero-padded blocks ----------------
__global__ void gather_adj(const float* __restrict__ adj) {
    int r = blockIdx.x;
    if (r >= d_poff[NSUB]) return;
    int s = find_sub(r);
    int local = r - d_poff[s];
    int ns = d_cnt[s];
    int nsp = d_poff[s + 1] - d_poff[s];
    long long base = d_abase[s] + (long long)local * nsp;
    __half z = __float2half(0.f);
    if (local >= ns) {
        for (int c = threadIdx.x; c < nsp; c += blockDim.x) d_Ag[base + c] = z;
        return;
    }
    int pr = d_perm[d_off[s] + local];
    const float* __restrict__ arow = adj + (size_t)pr * NN;
    const int* __restrict__ pcol = d_perm + d_off[s];
    for (int c = threadIdx.x; c < nsp; c += blockDim.x) {
        d_Ag[base + c] = (c < ns) ? __float2half(__ldg(arow + pcol[c]) * 8192.f) : z;
    }
}

// ---------------- tensor-core GEMM via mma.sync (HMMA), 128x128x64 staged ----------------
// MODE 0: S^T = (Xg @ Wt^T)^T      (writes transposed fp16 via smem transpose)
// MODE 1: out[perm[r]] = (1/8192) * Ag @ S^T^T
#define STAGE_BYTES 32768
#define GEMM_SMEM   (3 * STAGE_BYTES)     // 96 KB

template <int MODE>
__global__ __launch_bounds__(256, 1) void gemm_mma(float* __restrict__ out) {
    extern __shared__ char smem[];
    int tid = threadIdx.x, wid = tid >> 5, lane = tid & 31;
    int row0 = blockIdx.x * 128;
    if (row0 >= d_poff[NSUB]) return;
    int col0 = blockIdx.y * 128;
    int s = find_sub(row0);
    int ns = d_cnt[s];
    int nsp = d_poff[s + 1] - d_poff[s];
    int lrow0 = row0 - d_poff[s];

    const __half *A, *B;
    long long ldA, ldB;
    int K;
    if (MODE == 0) {
        A = d_Xg + (size_t)row0 * INF;  ldA = INF;
        B = d_Wt + ((size_t)s * OUTF + col0) * INF;  ldB = INF;
        K = INF;
    } else {
        A = d_Ag + d_abase[s] + (long long)lrow0 * nsp;  ldA = nsp;
        B = d_St + (size_t)col0 * TOTP + d_poff[s];      ldB = TOTP;
        K = nsp;
    }

    uint32_t sb = smem_u32(smem);

    // cooperative 128x(64 half)=128B-row tile load with SW128 swizzle, 16B chunks
    auto load_stage = [&](int buf, int kglob) {
        const __half* srcs[2] = {A, B};
        long long lds[2] = {ldA, ldB};
#pragma unroll
        for (int t = 0; t < 2; t++) {
            const __half* src = srcs[t];
            long long ld = lds[t];
            uint32_t tb = sb + buf * STAGE_BYTES + t * 16384;
#pragma unroll
            for (int i = 0; i < 4; i++) {
                int chunk = i * 256 + tid;           // 1024 chunks of 16B
                int row = chunk >> 3, cj = chunk & 7;
                const void* g = (const void*)(src + (long long)row * ld + kglob + cj * 8);
                CP_ASYNC16(tb + SW128(row * 128 + cj * 16), g);
            }
        }
        CP_COMMIT();
    };

    // warp tiling: 2 (m) x 4 (n) warps; warp tile 64m x 32n; frags 4m x 4n
    int warp_m = wid >> 2, warp_n = wid & 3;
    float acc[4][4][4];
#pragma unroll
    for (int i = 0; i < 4; i++)
#pragma unroll
        for (int j = 0; j < 4; j++)
#pragma unroll
            for (int q = 0; q < 4; q++) acc[i][j][q] = 0.f;

    // per-lane ldmatrix row indices
    int a_m = warp_m * 64 + (lane & 7) + ((lane >> 3) & 1) * 8;   // + mf*16
    int a_kc = (lane >> 4) & 1;                                    // + k16*2
    int b_n = warp_n * 32 + (lane & 7) + ((lane >> 4) & 1) * 8;    // + pair*16
    int b_kc = (lane >> 3) & 1;                                    // + k16*2

    int nst = K >> 6;
    load_stage(0, 0);
    load_stage(1, 64);

    for (int st = 0; st < nst; st++) {
        __syncthreads();   // everyone done reading buf[(st+2)%3] (stage st-1)
        if (st + 2 < nst) load_stage((st + 2) % 3, (st + 2) * 64);
        if (st + 2 < nst)      asm volatile("cp.async.wait_group 2;" ::: "memory");
        else if (st + 1 < nst) asm volatile("cp.async.wait_group 1;" ::: "memory");
        else                   asm volatile("cp.async.wait_group 0;" ::: "memory");
        __syncthreads();

        uint32_t ab = sb + (st % 3) * STAGE_BYTES;
        uint32_t bb = ab + 16384;
#pragma unroll
        for (int k16 = 0; k16 < 4; k16++) {
            uint32_t afr[4][4];
#pragma unroll
            for (int mf = 0; mf < 4; mf++) {
                int m = a_m + mf * 16;
                int kc = k16 * 2 + a_kc;
                LDSM_X4(afr[mf][0], afr[mf][1], afr[mf][2], afr[mf][3],
                        ab + SW128(m * 128 + kc * 16));
            }
            uint32_t bfr[4][2];
#pragma unroll
            for (int p = 0; p < 2; p++) {
                int n = b_n + p * 16;
                int kc = k16 * 2 + b_kc;
                uint32_t r0, r1, r2, r3;
                LDSM_X4(r0, r1, r2, r3, bb + SW128(n * 128 + kc * 16));
                bfr[2 * p][0] = r0; bfr[2 * p][1] = r1;
                bfr[2 * p + 1][0] = r2; bfr[2 * p + 1][1] = r3;
            }
#pragma unroll
            for (int mf = 0; mf < 4; mf++)
#pragma unroll
                for (int nf = 0; nf < 4; nf++)
                    MMA_F16(acc[mf][nf], afr[mf], bfr[nf]);
        }
    }

    // ---------------- epilogue ----------------
    if (MODE == 0) {
        // transpose through smem, then coalesced fp16 store of S^T tile [n][m]
        __syncthreads();
        __half* Ssm = (__half*)smem;   // [128 n][128 m] = 32 KB
#pragma unroll
        for (int mf = 0; mf < 4; mf++)
#pragma unroll
            for (int nf = 0; nf < 4; nf++) {
                int r = warp_m * 64 + mf * 16 + (lane >> 2);
                int c = warp_n * 32 + nf * 8 + (lane & 3) * 2;
                Ssm[(c + 0) * 128 + r]     = __float2half(acc[mf][nf][0]);
                Ssm[(c + 1) * 128 + r]     = __float2half(acc[mf][nf][1]);
                Ssm[(c + 0) * 128 + r + 8] = __float2half(acc[mf][nf][2]);
                Ssm[(c + 1) * 128 + r + 8] = __float2half(acc[mf][nf][3]);
            }
        __syncthreads();
#pragma unroll
        for (int i = 0; i < 8; i++) {
            int chunk = i * 256 + tid;          // 2048 chunks of 16B (8 halves)
            int n = chunk >> 4, seg = chunk & 15;
            uint4 v = *(uint4*)((char*)smem + n * 256 + seg * 16);
            *(uint4*)(d_St + (size_t)(col0 + n) * TOTP + row0 + seg * 8) = v;
        }
    } else {
        const float sc = 1.f / 8192.f;
#pragma unroll
        for (int mf = 0; mf < 4; mf++) {
            int r = warp_m * 64 + mf * 16 + (lane >> 2);
            int lr0 = lrow0 + r, lr1 = lrow0 + r + 8;
            float* o0 = (lr0 < ns) ? out + (size_t)d_perm[d_off[s] + lr0] * OUTF + col0 : nullptr;
            float* o1 = (lr1 < ns) ? out + (size_t)d_perm[d_off[s] + lr1] * OUTF + col0 : nullptr;
#pragma unroll
            for (int nf = 0; nf < 4; nf++) {
                int c = nf * 8 + (lane & 3) * 2 + warp_n * 32;
                if (o0) *(float2*)(o0 + c) = make_float2(acc[mf][nf][0] * sc, acc[mf][nf][1] * sc);
                if (o1) *(float2*)(o1 + c) = make_float2(acc[mf][nf][2] * sc, acc[mf][nf][3] * sc);
            }
        }
    }
}

// ---------------- launch ----------------
extern "C" void kernel_launch(void* const* d_in, const int* in_sizes, int n_in,
                              void* d_out, int out_size) {
    const float* X      = (const float*)d_in[0];   // [8192, 512]
    const float* adj    = (const float*)d_in[1];   // [8192, 8192]
    const int*   labels = (const int*)d_in[2];     // [8192]
    const float* W      = (const float*)d_in[3];   // [8, 512, 512]
    float* out = (float*)d_out;                    // [8192, 512]

    cudaFuncSetAttribute(gemm_mma<0>, cudaFuncAttributeMaxDynamicSharedMemorySize, GEMM_SMEM);
    cudaFuncSetAttribute(gemm_mma<1>, cudaFuncAttributeMaxDynamicSharedMemorySize, GEMM_SMEM);

    build_perm<<<1, 256>>>(labels);
    prep_W<<<dim3(INF / 32, OUTF / 32, NSUB), dim3(32, 8)>>>(W);
    prep_X<<<TOTP, 128>>>(X);
    gather_adj<<<TOTP, 256>>>(adj);
    gemm_mma<0><<<dim3(TOTP / 128, OUTF / 128), 256, GEMM_SMEM>>>(nullptr);
    gemm_mma<1><<<dim3(TOTP / 128, OUTF / 128), 256, GEMM_SMEM>>>(out);
}